// round 12
// baseline (speedup 1.0000x reference)
#include <cuda_runtime.h>
#include <cuda_bf16.h>
#include <math.h>
#include <stdint.h>

#define B_ 64
#define S_ 512
#define I_ 256
#define H_ 1024
#define O_ 128
#define BK 32

// ---------------- static device scratch (no dynamic allocation) ------------
__device__ __nv_bfloat16 g_buf[((size_t)B_ * S_ + 32) * H_]; // g2=(1-a)(1-b)(ff+bias), bf16 (+32 rows prefetch pad)
__device__ __nv_bfloat16 xbf[(size_t)B_ * S_ * I_];          // x in bf16
__device__ __nv_bfloat16 wbf[(size_t)H_ * I_];               // W_in in bf16
__device__ unsigned      spk_buf[(size_t)B_ * S_ * (H_ / 32)];
__device__ float         s1_buf[H_];                          // (1-alpha)(1-beta)
__device__ float         s2_buf[H_];                          // b_in + b_rec
__device__ unsigned      chunk_sync[B_ * 8];                  // per (batch,chunk) cross-CTA combine
__device__ unsigned      step_sync[B_ * S_];                  // per (batch,step) combine (replay path)

__device__ __forceinline__ float sigmoidf_(float x) { return 1.f / (1.f + expf(-x)); }

__device__ __forceinline__ uint32_t smem_u32(const void* p) {
    uint32_t a;
    asm("{ .reg .u64 t; cvta.to.shared.u64 t, %1; cvt.u32.u64 %0, t; }" : "=r"(a) : "l"(p));
    return a;
}
__device__ __forceinline__ void cp_async16(uint32_t dst, const void* src) {
    asm volatile("cp.async.cg.shared.global [%0], [%1], 16;" :: "r"(dst), "l"(src) : "memory");
}
__device__ __forceinline__ void cp_commit() {
    asm volatile("cp.async.commit_group;" ::: "memory");
}
__device__ __forceinline__ void ldmatrix_x4(unsigned& r0, unsigned& r1, unsigned& r2, unsigned& r3,
                                            uint32_t addr) {
    asm volatile("ldmatrix.sync.aligned.m8n8.x4.shared.b16 {%0,%1,%2,%3}, [%4];"
                 : "=r"(r0), "=r"(r1), "=r"(r2), "=r"(r3) : "r"(addr));
}

// ---------------------------------------------------------------------------
// Phase 0: conversions + constants + flag zeroing, MLP=4 per thread.
// blocks 0..511: x -> bf16 ; 512..527: W_in -> bf16 ; 528: consts+chunk flags;
// 529..536: step flags.
// ---------------------------------------------------------------------------
__global__ void cvt_kernel(const float* __restrict__ x, const float* __restrict__ W_in,
                           const float* __restrict__ b_in, const float* __restrict__ b_rec,
                           const float* __restrict__ tau_m, const float* __restrict__ tau_n) {
    int bid = blockIdx.x, tid = threadIdx.x;
    if (bid < 512) {
        const float4* xin = (const float4*)x + (size_t)bid * 4096 + tid;
        uint2* xo = (uint2*)xbf + (size_t)bid * 4096 + tid;
        float4 v[4];
#pragma unroll
        for (int i = 0; i < 4; i++) v[i] = xin[i * 1024];
#pragma unroll
        for (int i = 0; i < 4; i++) {
            __nv_bfloat162 a = __floats2bfloat162_rn(v[i].x, v[i].y);
            __nv_bfloat162 b2 = __floats2bfloat162_rn(v[i].z, v[i].w);
            xo[i * 1024] = make_uint2(*(unsigned*)&a, *(unsigned*)&b2);
        }
    } else if (bid < 528) {
        int base = (bid - 512) * 4096 + tid;
        const float4* wi = (const float4*)W_in;
        uint2* wo = (uint2*)wbf;
        float4 v[4];
#pragma unroll
        for (int i = 0; i < 4; i++) v[i] = wi[base + i * 1024];
#pragma unroll
        for (int i = 0; i < 4; i++) {
            __nv_bfloat162 a = __floats2bfloat162_rn(v[i].x, v[i].y);
            __nv_bfloat162 b2 = __floats2bfloat162_rn(v[i].z, v[i].w);
            wo[base + i * 1024] = make_uint2(*(unsigned*)&a, *(unsigned*)&b2);
        }
    } else if (bid == 528) {
        int h = tid;
        float a1 = 1.f - sigmoidf_(tau_m[h]);
        float b1 = 1.f - sigmoidf_(tau_n[h]);
        s1_buf[h] = a1 * b1;
        s2_buf[h] = b_in[h] + b_rec[h];
        if (tid < B_ * 8) chunk_sync[tid] = 0;
    } else {
        int base = (bid - 529) * 4096 + tid;
#pragma unroll
        for (int i = 0; i < 4; i++) step_sync[base + i * 1024] = 0;
    }
}

// ---------------------------------------------------------------------------
// Phase 1: HMMA GEMM with ldmatrix fragments + persistent B tile.
// g[m][n] = s1[n]*(X[m,:]·W[n,:] + s2[n]), bf16 out.
// Grid = 8 N-tiles x 128 M-groups = 1024 CTAs, 256 thr, 2 CTAs/SM.
// Each CTA: B tile (128x256 bf16, row stride 528B, conflict-free) loaded ONCE;
// 2 M-tiles of 128 streamed through a 3-stage cp.async A pipeline (row 80B).
// ---------------------------------------------------------------------------
#define ASTG   10240                     // 128 rows * 80B
#define SM_B   (3 * ASTG)                // 30720
#define BROW   528
#define SM_S12 (SM_B + 128 * BROW)       // 98304
#define SMEM_BYTES (SM_S12 + 128 * 8)    // 99328

__global__ __launch_bounds__(256, 2)
void ff_gemm_kernel() {
    extern __shared__ char smem[];
    uint32_t sa  = smem_u32(smem);
    uint32_t sbm = sa + SM_B;
    float2* s12 = (float2*)(smem + SM_S12);

    int tid = threadIdx.x, lane = tid & 31, warp = tid >> 5;
    int nt = blockIdx.x & 7, mg = blockIdx.x >> 3;
    int n0 = nt * 128;

    if (tid < 128) s12[tid] = make_float2(s1_buf[n0 + tid], s2_buf[n0 + tid]);

    // B preload: 128 rows x 512B = 4096 16B chunks, 16 per thread
    const __nv_bfloat16* Bb = wbf + (size_t)n0 * I_;
#pragma unroll
    for (int i = 0; i < 16; i++) {
        int idx = tid + i * 256; int row = idx >> 5; int c = idx & 31;
        cp_async16(sbm + row * BROW + c * 16, Bb + (size_t)row * I_ + c * 8);
    }
    cp_commit();

    const __nv_bfloat16* Am = xbf + (size_t)mg * 2 * 128 * I_;
    int ar0 = (tid * 2) >> 2, ac0 = (tid * 2) & 3;
    int ar1 = (tid * 2 + 1) >> 2, ac1 = (tid * 2 + 1) & 3;

#define ISSUE(j) do { int st = (j) % 3;                                          \
        const __nv_bfloat16* Ab = Am + (size_t)((j) >> 3) * 128 * I_ + ((j) & 7) * BK; \
        cp_async16(sa + st * ASTG + ar0 * 80 + ac0 * 16, Ab + (size_t)ar0 * I_ + ac0 * 8); \
        cp_async16(sa + st * ASTG + ar1 * 80 + ac1 * 16, Ab + (size_t)ar1 * I_ + ac1 * 8); \
        cp_commit(); } while (0)

    ISSUE(0);
    ISSUE(1);

    int wm = (warp >> 2) * 64;   // 0 or 64
    int wn = (warp & 3) * 32;    // 0..96
    int fr = lane >> 2, fc = (lane & 3) * 2;
    // ldmatrix lane address components
    int a_row = (lane & 7) + ((lane >> 3) & 1) * 8;
    int a_c16 = (lane >> 4) * 16;
    int b_row = wn + ((lane >> 4) & 1) * 8 + (lane & 7);
    int b_c16 = ((lane >> 3) & 1) * 16;

    float acc[4][4][4];
#pragma unroll
    for (int i = 0; i < 4; i++)
#pragma unroll
        for (int j = 0; j < 4; j++)
#pragma unroll
            for (int r = 0; r < 4; r++) acc[i][j][r] = 0.f;

    for (int it = 0; it < 16; it++) {
        if (it < 15) asm volatile("cp.async.wait_group 1;" ::: "memory");
        else         asm volatile("cp.async.wait_group 0;" ::: "memory");
        __syncthreads();
        if (it + 2 < 16) ISSUE(it + 2);

        uint32_t abuf = sa + (it % 3) * ASTG;
        int ktc = (it & 7) * 64;   // byte offset of this k-tile within a B row
#pragma unroll
        for (int ks = 0; ks < 2; ks++) {
            unsigned afr[4][4], bfr[4][2];
#pragma unroll
            for (int mi = 0; mi < 4; mi++) {
                uint32_t addr = abuf + (wm + mi * 16 + a_row) * 80 + ks * 32 + a_c16;
                ldmatrix_x4(afr[mi][0], afr[mi][1], afr[mi][2], afr[mi][3], addr);
            }
#pragma unroll
            for (int p = 0; p < 2; p++) {
                uint32_t addr = sbm + (b_row + p * 16) * BROW + ktc + ks * 32 + b_c16;
                ldmatrix_x4(bfr[2 * p][0], bfr[2 * p][1], bfr[2 * p + 1][0], bfr[2 * p + 1][1], addr);
            }
#pragma unroll
            for (int mi = 0; mi < 4; mi++)
#pragma unroll
                for (int ni = 0; ni < 4; ni++) {
                    asm volatile(
                        "mma.sync.aligned.m16n8k16.row.col.f32.bf16.bf16.f32 "
                        "{%0,%1,%2,%3}, {%4,%5,%6,%7}, {%8,%9}, {%0,%1,%2,%3};"
                        : "+f"(acc[mi][ni][0]), "+f"(acc[mi][ni][1]),
                          "+f"(acc[mi][ni][2]), "+f"(acc[mi][ni][3])
                        : "r"(afr[mi][0]), "r"(afr[mi][1]), "r"(afr[mi][2]), "r"(afr[mi][3]),
                          "r"(bfr[ni][0]), "r"(bfr[ni][1]));
                }
        }

        if ((it & 7) == 7) {
            // epilogue for M-tile (it>>3): g = s1*(c + s2), bf16
            int m0 = (mg * 2 + (it >> 3)) * 128;
#pragma unroll
            for (int mi = 0; mi < 4; mi++) {
#pragma unroll
                for (int ni = 0; ni < 4; ni++) {
                    int nloc = wn + ni * 8 + fc;
                    int n = n0 + nloc;
                    float2 pa = s12[nloc], pb = s12[nloc + 1];
                    int ma = m0 + wm + mi * 16 + fr;
                    *(__nv_bfloat162*)&g_buf[(size_t)ma * H_ + n] =
                        __floats2bfloat162_rn(pa.x * (acc[mi][ni][0] + pa.y),
                                              pb.x * (acc[mi][ni][1] + pb.y));
                    *(__nv_bfloat162*)&g_buf[(size_t)(ma + 8) * H_ + n] =
                        __floats2bfloat162_rn(pa.x * (acc[mi][ni][2] + pa.y),
                                              pb.x * (acc[mi][ni][3] + pb.y));
                    acc[mi][ni][0] = acc[mi][ni][1] = acc[mi][ni][2] = acc[mi][ni][3] = 0.f;
                }
            }
        }
    }
#undef ISSUE
}

// ---------------------------------------------------------------------------
// Phase 2: speculative chunked scan + fused output. 2 CTAs per batch,
// 256 threads, 2 adjacent neurons per thread (bf162 loads).
// D = beta*D + g2 (+ s1c*rec); mem = alpha*mem + D; spike iff mem>1.
// Fast path per 64-step chunk: ONE block barrier + ONE cross-CTA combine,
// then hb==0 writes out rows = sigmoid(b_out) directly.
// Cold path: exact per-step replay (smem atomicOr masks + sparse W_rec gather
// + per-step cross-CTA sync + sparse W_out output).
// ---------------------------------------------------------------------------
__global__ __launch_bounds__(256, 1)
void scan_kernel(const float* __restrict__ tau_m, const float* __restrict__ tau_n,
                 const float* __restrict__ W_rec, const float* __restrict__ W_out,
                 const float* __restrict__ b_out, float* __restrict__ out) {
    __shared__ __align__(16) float sig[O_];   // 16B-aligned: read as float4 below
    __shared__ int s_any;
    __shared__ unsigned smask[16];
    int bc = blockIdx.x;           // 0..127
    int b = bc >> 1, hb = bc & 1;
    int tid = threadIdx.x;
    int h0 = hb * 512 + tid * 2;

    float al0 = sigmoidf_(tau_m[h0]), al1 = sigmoidf_(tau_m[h0 + 1]);
    float be0 = sigmoidf_(tau_n[h0]), be1 = sigmoidf_(tau_n[h0 + 1]);
    float s10 = (1.f - al0) * (1.f - be0), s11 = (1.f - al1) * (1.f - be1);
    const __nv_bfloat162* gp = (const __nv_bfloat162*)(g_buf + (size_t)b * S_ * H_ + h0);
    unsigned* spkrow = spk_buf + (size_t)b * S_ * 32;
    const float* wr0 = W_rec + (size_t)h0 * H_;
    const float* wr1 = W_rec + (size_t)(h0 + 1) * H_;
    float* outb = out + (size_t)b * S_ * O_;

    if (tid < O_) sig[tid] = sigmoidf_(b_out[tid]);
    __syncthreads();

    float m0 = 0.f, m1 = 0.f, d0 = 0.f, d1 = 0.f;
    __nv_bfloat162 ring[16];
#pragma unroll
    for (int i = 0; i < 16; i++) ring[i] = gp[(size_t)i * (H_ / 2)];
    const __nv_bfloat162* pf = gp + (size_t)16 * (H_ / 2);   // g_buf has +32 rows pad

    int carry = 0;
    for (int chunk = 0; chunk < 8; chunk++) {
        int base = chunk * 64;
        float sm0 = m0, sm1 = m1, sd0 = d0, sd1 = d1, maxm = 0.f;
        for (int u = 0; u < 4; u++) {
#pragma unroll
            for (int v = 0; v < 16; v++) {
                __nv_bfloat162 g2 = ring[v];
                ring[v] = *pf; pf += H_ / 2;
                float f0 = __low2float(g2), f1 = __high2float(g2);
                d0 = fmaf(be0, d0, f0); m0 = fmaf(al0, m0, d0);
                d1 = fmaf(be1, d1, f1); m1 = fmaf(al1, m1, d1);
                maxm = fmaxf(maxm, fmaxf(m0, m1));
            }
        }
        int lany = __syncthreads_or(maxm > 1.f);
        if (tid == 0) {
            __threadfence();
            atomicAdd(&chunk_sync[b * 8 + chunk], 0x10000u | (unsigned)lany);
            unsigned v;
            do { v = *((volatile unsigned*)&chunk_sync[b * 8 + chunk]); } while ((v >> 16) < 2u);
            __threadfence();
            s_any = (int)(v & 0xFFFFu);
        }
        __syncthreads();
        int any = s_any;
        __syncthreads();

        if (!(any | carry)) {
            if (hb == 0) {
                float4* o4 = (float4*)(outb + (size_t)base * O_);
                const float4* s4 = (const float4*)sig;
#pragma unroll
                for (int i = 0; i < 8; i++) {
                    int idx = tid + i * 256;           // 2048 float4 = 64 rows x 32
                    o4[idx] = s4[idx & 31];
                }
            }
            carry = 0;
        } else {
            // exact replay of this chunk (cold path)
            m0 = sm0; m1 = sm1; d0 = sd0; d1 = sd1;
            int prev = carry;
            for (int tt = 0; tt < 64; tt++) {
                int t = base + tt;
                float r0 = 0.f, r1 = 0.f;
                if (prev) {
                    const unsigned* mrow = spkrow + (size_t)(t - 1) * 32;
                    for (int w2 = 0; w2 < 32; w2++) {
                        unsigned msk = mrow[w2];
                        while (msk) {
                            int j = __ffs((int)msk) - 1;
                            r0 += wr0[w2 * 32 + j];
                            r1 += wr1[w2 * 32 + j];
                            msk &= msk - 1;
                        }
                    }
                }
                __nv_bfloat162 g2 = gp[(size_t)t * (H_ / 2)];
                float f0 = __low2float(g2), f1 = __high2float(g2);
                d0 = fmaf(be0, d0, fmaf(s10, r0, f0)); m0 = fmaf(al0, m0, d0);
                d1 = fmaf(be1, d1, fmaf(s11, r1, f1)); m1 = fmaf(al1, m1, d1);
                int sp0 = m0 > 1.f, sp1 = m1 > 1.f;
                if (sp0) m0 = 0.f;
                if (sp1) m1 = 0.f;
                if (tid < 16) smask[tid] = 0;
                __syncthreads();
                unsigned val = (((unsigned)sp0) | (((unsigned)sp1) << 1)) << ((tid * 2) & 31);
                if (val) atomicOr(&smask[tid >> 4], val);
                int lor = __syncthreads_or(sp0 | sp1);
                if (tid < 16) spkrow[(size_t)t * 32 + hb * 16 + tid] = smask[tid];
                __syncthreads();
                if (tid == 0) {
                    __threadfence();
                    atomicAdd(&step_sync[b * S_ + t], 0x10000u | (unsigned)lor);
                    unsigned v;
                    do { v = *((volatile unsigned*)&step_sync[b * S_ + t]); } while ((v >> 16) < 2u);
                    __threadfence();
                    s_any = (int)(v & 0xFFFFu);
                }
                __syncthreads();
                prev = s_any ? 1 : 0;
                __syncthreads();
                if (hb == 0 && tid < 128) {
                    // out[b,t,tid] = sigmoid(b_out + sum_{j spiking} W_out[tid][j])
                    float acc = b_out[tid];
                    const unsigned* mrow = spkrow + (size_t)t * 32;
                    for (int w2 = 0; w2 < 32; w2++) {
                        unsigned msk = mrow[w2];
                        while (msk) {
                            int j = __ffs((int)msk) - 1;
                            acc += W_out[(size_t)tid * H_ + w2 * 32 + j];
                            msk &= msk - 1;
                        }
                    }
                    outb[(size_t)t * O_ + tid] = sigmoidf_(acc);
                }
            }
            carry = prev;
        }
    }
}

// ---------------------------------------------------------------------------
extern "C" void kernel_launch(void* const* d_in, const int* in_sizes, int n_in,
                              void* d_out, int out_size) {
    const float* x     = (const float*)d_in[0];
    const float* W_in  = (const float*)d_in[1];
    const float* b_in  = (const float*)d_in[2];
    const float* W_rec = (const float*)d_in[3];
    const float* b_rec = (const float*)d_in[4];
    const float* tau_m = (const float*)d_in[5];
    const float* tau_n = (const float*)d_in[6];
    const float* W_out = (const float*)d_in[7];
    const float* b_out = (const float*)d_in[8];
    float* out = (float*)d_out;

    static int attr_done = 0;
    if (!attr_done) {
        cudaFuncSetAttribute(ff_gemm_kernel, cudaFuncAttributeMaxDynamicSharedMemorySize, SMEM_BYTES);
        attr_done = 1;
    }

    cvt_kernel<<<537, 1024>>>(x, W_in, b_in, b_rec, tau_m, tau_n);
    ff_gemm_kernel<<<1024, 256, SMEM_BYTES>>>();
    scan_kernel<<<128, 256>>>(tau_m, tau_n, W_rec, W_out, b_out, out);
}

// round 13
// speedup vs baseline: 1.3619x; 1.3619x over previous
#include <cuda_runtime.h>
#include <cuda_bf16.h>
#include <math.h>
#include <stdint.h>

#define B_ 64
#define S_ 512
#define I_ 256
#define H_ 1024
#define O_ 128

// ---------------- static device scratch (no dynamic allocation) ------------
__device__ __nv_bfloat16 g_buf[((size_t)B_ * S_ + 32) * H_]; // g2=(1-a)(1-b)(ff+bias), bf16 (+32 rows prefetch pad)
__device__ __nv_bfloat16 xbf[(size_t)B_ * S_ * I_];          // x in bf16
__device__ __nv_bfloat16 wbf[(size_t)H_ * I_];               // W_in in bf16
__device__ unsigned      spk_buf[(size_t)B_ * S_ * (H_ / 32)];
__device__ float         s1_buf[H_];                          // (1-alpha)(1-beta)
__device__ float         s2_buf[H_];                          // b_in + b_rec
__device__ unsigned      chunk_sync[B_ * 8];                  // per (batch,chunk) cross-CTA combine
__device__ unsigned      step_sync[B_ * S_];                  // per (batch,step) combine (replay path)

__device__ __forceinline__ float sigmoidf_(float x) { return 1.f / (1.f + expf(-x)); }

__device__ __forceinline__ uint32_t smem_u32(const void* p) {
    uint32_t a;
    asm("{ .reg .u64 t; cvta.to.shared.u64 t, %1; cvt.u32.u64 %0, t; }" : "=r"(a) : "l"(p));
    return a;
}
__device__ __forceinline__ void cp_async16(uint32_t dst, const void* src) {
    asm volatile("cp.async.cg.shared.global [%0], [%1], 16;" :: "r"(dst), "l"(src) : "memory");
}
__device__ __forceinline__ void cp_commit() {
    asm volatile("cp.async.commit_group;" ::: "memory");
}

// ---------------------------------------------------------------------------
// Phase 0 (measured 11.4us): conversions + constants + flag zeroing, MLP=4.
// blocks 0..511: x -> bf16 ; 512..527: W_in -> bf16 ; 528: consts+chunk flags;
// 529..536: step flags.
// ---------------------------------------------------------------------------
__global__ void cvt_kernel(const float* __restrict__ x, const float* __restrict__ W_in,
                           const float* __restrict__ b_in, const float* __restrict__ b_rec,
                           const float* __restrict__ tau_m, const float* __restrict__ tau_n) {
    int bid = blockIdx.x, tid = threadIdx.x;
    if (bid < 512) {
        const float4* xin = (const float4*)x + (size_t)bid * 4096 + tid;
        uint2* xo = (uint2*)xbf + (size_t)bid * 4096 + tid;
        float4 v[4];
#pragma unroll
        for (int i = 0; i < 4; i++) v[i] = xin[i * 1024];
#pragma unroll
        for (int i = 0; i < 4; i++) {
            __nv_bfloat162 a = __floats2bfloat162_rn(v[i].x, v[i].y);
            __nv_bfloat162 b2 = __floats2bfloat162_rn(v[i].z, v[i].w);
            xo[i * 1024] = make_uint2(*(unsigned*)&a, *(unsigned*)&b2);
        }
    } else if (bid < 528) {
        int base = (bid - 512) * 4096 + tid;
        const float4* wi = (const float4*)W_in;
        uint2* wo = (uint2*)wbf;
        float4 v[4];
#pragma unroll
        for (int i = 0; i < 4; i++) v[i] = wi[base + i * 1024];
#pragma unroll
        for (int i = 0; i < 4; i++) {
            __nv_bfloat162 a = __floats2bfloat162_rn(v[i].x, v[i].y);
            __nv_bfloat162 b2 = __floats2bfloat162_rn(v[i].z, v[i].w);
            wo[base + i * 1024] = make_uint2(*(unsigned*)&a, *(unsigned*)&b2);
        }
    } else if (bid == 528) {
        int h = tid;
        float a1 = 1.f - sigmoidf_(tau_m[h]);
        float b1 = 1.f - sigmoidf_(tau_n[h]);
        s1_buf[h] = a1 * b1;
        s2_buf[h] = b_in[h] + b_rec[h];
        if (tid < B_ * 8) chunk_sync[tid] = 0;
    } else {
        int base = (bid - 529) * 4096 + tid;
#pragma unroll
        for (int i = 0; i < 4; i++) step_sync[base + i * 1024] = 0;
    }
}

// ---------------------------------------------------------------------------
// Phase 1 (restored from the 131.6us run): HMMA GEMM.
// g[m][n] = s1[n]*(X[m,:]·W[n,:] + s2[n]), bf16 out.
// C[32768,1024] = Xbf @ Wbf^T. BM=BN=128, BK=32, 8 warps (64x32 each),
// 3-stage cp.async pipeline, padded smem rows (40 bf16). 2 CTAs/SM.
// ---------------------------------------------------------------------------
#define BK 32
#define PAD 40
#define STG_BYTES (128 * PAD * 2)          // 10240 B per stage per matrix
#define SM_AS 0
#define SM_BS (3 * STG_BYTES)              // 30720
#define SM_S12 (6 * STG_BYTES)             // 61440
#define SMEM_BYTES (SM_S12 + 128 * 8)      // 62464

__global__ __launch_bounds__(256, 2)
void ff_gemm_kernel() {
    extern __shared__ char smem[];
    uint32_t sa = smem_u32(smem) + SM_AS;
    uint32_t sbm = smem_u32(smem) + SM_BS;
    float2* s12 = (float2*)(smem + SM_S12);

    int tid = threadIdx.x, lane = tid & 31, warp = tid >> 5;
    int nt = blockIdx.x & 7, mt = blockIdx.x >> 3;
    int m0 = mt * 128, n0 = nt * 128;

    if (tid < 128) s12[tid] = make_float2(s1_buf[n0 + tid], s2_buf[n0 + tid]);

    // per-thread load slots: 512 16B chunks per tile per matrix, 2 each
    int r0 = (tid * 2) >> 2, c0 = (tid * 2) & 3;
    int r1 = (tid * 2 + 1) >> 2, c1 = (tid * 2 + 1) & 3;
    const __nv_bfloat16* Abase = xbf + (size_t)m0 * I_;
    const __nv_bfloat16* Bbase = wbf + (size_t)n0 * I_;

#define ISSUE(kt) do {                                                          \
        int st = (kt) % 3; int k0 = (kt) * BK;                                  \
        cp_async16(sa  + st * STG_BYTES + r0 * (PAD * 2) + c0 * 16,             \
                   Abase + (size_t)r0 * I_ + k0 + c0 * 8);                      \
        cp_async16(sa  + st * STG_BYTES + r1 * (PAD * 2) + c1 * 16,             \
                   Abase + (size_t)r1 * I_ + k0 + c1 * 8);                      \
        cp_async16(sbm + st * STG_BYTES + r0 * (PAD * 2) + c0 * 16,             \
                   Bbase + (size_t)r0 * I_ + k0 + c0 * 8);                      \
        cp_async16(sbm + st * STG_BYTES + r1 * (PAD * 2) + c1 * 16,             \
                   Bbase + (size_t)r1 * I_ + k0 + c1 * 8);                      \
        cp_commit();                                                            \
    } while (0)

    ISSUE(0);
    ISSUE(1);

    int wm = (warp >> 2) * 64;   // 0 or 64
    int wn = (warp & 3) * 32;    // 0..96
    int fr = lane >> 2, fc = (lane & 3) * 2;

    float acc[4][4][4];
#pragma unroll
    for (int i = 0; i < 4; i++)
#pragma unroll
        for (int j = 0; j < 4; j++)
#pragma unroll
            for (int r = 0; r < 4; r++) acc[i][j][r] = 0.f;

    for (int kt = 0; kt < 8; kt++) {
        if (kt < 7) asm volatile("cp.async.wait_group 1;" ::: "memory");
        else        asm volatile("cp.async.wait_group 0;" ::: "memory");
        __syncthreads();
        if (kt + 2 < 8) ISSUE(kt + 2);

        uint32_t abuf = sa  + (kt % 3) * STG_BYTES;
        uint32_t bbuf = sbm + (kt % 3) * STG_BYTES;
#pragma unroll
        for (int ks = 0; ks < 2; ks++) {
            unsigned afr[4][4], bfr[4][2];
#pragma unroll
            for (int mi = 0; mi < 4; mi++) {
                int rb = wm + mi * 16;
                uint32_t base = abuf + (rb + fr) * (PAD * 2) + (ks * 16 + fc) * 2;
                asm("ld.shared.b32 %0, [%1];" : "=r"(afr[mi][0]) : "r"(base));
                asm("ld.shared.b32 %0, [%1];" : "=r"(afr[mi][1]) : "r"(base + 8 * PAD * 2));
                asm("ld.shared.b32 %0, [%1];" : "=r"(afr[mi][2]) : "r"(base + 16));
                asm("ld.shared.b32 %0, [%1];" : "=r"(afr[mi][3]) : "r"(base + 8 * PAD * 2 + 16));
            }
#pragma unroll
            for (int ni = 0; ni < 4; ni++) {
                int cb = wn + ni * 8 + fr;
                uint32_t base = bbuf + cb * (PAD * 2) + (ks * 16 + fc) * 2;
                asm("ld.shared.b32 %0, [%1];" : "=r"(bfr[ni][0]) : "r"(base));
                asm("ld.shared.b32 %0, [%1];" : "=r"(bfr[ni][1]) : "r"(base + 16));
            }
#pragma unroll
            for (int mi = 0; mi < 4; mi++)
#pragma unroll
                for (int ni = 0; ni < 4; ni++) {
                    asm volatile(
                        "mma.sync.aligned.m16n8k16.row.col.f32.bf16.bf16.f32 "
                        "{%0,%1,%2,%3}, {%4,%5,%6,%7}, {%8,%9}, {%0,%1,%2,%3};"
                        : "+f"(acc[mi][ni][0]), "+f"(acc[mi][ni][1]),
                          "+f"(acc[mi][ni][2]), "+f"(acc[mi][ni][3])
                        : "r"(afr[mi][0]), "r"(afr[mi][1]), "r"(afr[mi][2]), "r"(afr[mi][3]),
                          "r"(bfr[ni][0]), "r"(bfr[ni][1]));
                }
        }
        __syncthreads();
    }

    // Epilogue: g = s1*(c + s2), bf16
#pragma unroll
    for (int mi = 0; mi < 4; mi++) {
#pragma unroll
        for (int ni = 0; ni < 4; ni++) {
            int nloc = wn + ni * 8 + fc;
            int n = n0 + nloc;
            float2 pa = s12[nloc], pb = s12[nloc + 1];
            int ma = m0 + wm + mi * 16 + fr;
            *(__nv_bfloat162*)&g_buf[(size_t)ma * H_ + n] =
                __floats2bfloat162_rn(pa.x * (acc[mi][ni][0] + pa.y), pb.x * (acc[mi][ni][1] + pb.y));
            *(__nv_bfloat162*)&g_buf[(size_t)(ma + 8) * H_ + n] =
                __floats2bfloat162_rn(pa.x * (acc[mi][ni][2] + pa.y), pb.x * (acc[mi][ni][3] + pb.y));
        }
    }
#undef ISSUE
}

// ---------------------------------------------------------------------------
// Phase 2 (restored from the passing R8 run): speculative chunked scan +
// fused output. 4 CTAs per batch (256 neurons each, 256 CTAs co-resident).
// D = beta*D + g2 (+ s1c*rec); mem = alpha*mem + D; spike iff mem>1.
// Fast path per 64-step chunk: ONE block barrier + ONE cross-CTA combine,
// then sub==0 writes out rows = sigmoid(b_out) directly.
// Cold path: exact per-step replay (ballot + sparse W_rec gather + per-step
// cross-CTA sync + sparse W_out output).
// ---------------------------------------------------------------------------
__global__ __launch_bounds__(256, 1)
void scan_kernel(const float* __restrict__ tau_m, const float* __restrict__ tau_n,
                 const float* __restrict__ W_rec, const float* __restrict__ W_out,
                 const float* __restrict__ b_out, float* __restrict__ out) {
    __shared__ int s_any;
    __shared__ float4 sig4[32];
    int bc = blockIdx.x;          // 0..255
    int b = bc >> 2, sub = bc & 3;
    int tid = threadIdx.x;
    int h = sub * 256 + tid;

    float alpha = sigmoidf_(tau_m[h]);
    float beta  = sigmoidf_(tau_n[h]);
    float s1c = (1.f - alpha) * (1.f - beta);
    const __nv_bfloat16* gp = g_buf + (size_t)b * S_ * H_ + h;
    unsigned* spkrow = spk_buf + (size_t)b * S_ * 32;
    const float* wr = W_rec + (size_t)h * H_;
    float* outb = out + (size_t)b * S_ * O_;

    if (tid < 128) ((float*)sig4)[tid] = sigmoidf_(b_out[tid]);
    __syncthreads();

    float mem = 0.f, D = 0.f;
    __nv_bfloat16 ring[32];
#pragma unroll
    for (int i = 0; i < 32; i++) ring[i] = gp[(size_t)i * H_];
    const __nv_bfloat16* pf = gp + (size_t)32 * H_;   // g_buf has +32 rows pad

    int carry = 0;
    for (int chunk = 0; chunk < 8; chunk++) {
        int base = chunk * 64;
        float mem0 = mem, D0 = D, maxm = 0.f;
        for (int u = 0; u < 2; u++) {
#pragma unroll
            for (int v = 0; v < 32; v++) {
                float gv = __bfloat162float(ring[v]);
                ring[v] = *pf; pf += H_;
                D = fmaf(beta, D, gv);
                mem = fmaf(alpha, mem, D);
                maxm = fmaxf(maxm, mem);
            }
        }
        int lany = __syncthreads_or(maxm > 1.f);
        if (tid == 0) {
            __threadfence();
            atomicAdd(&chunk_sync[b * 8 + chunk], 0x10000u | (unsigned)lany);
            unsigned v;
            do { v = *((volatile unsigned*)&chunk_sync[b * 8 + chunk]); } while ((v >> 16) < 4u);
            __threadfence();
            s_any = (int)(v & 0xFFFFu);
        }
        __syncthreads();
        int any = s_any;
        __syncthreads();

        if (!(any | carry)) {
            if (sub == 0) {
                float4* o4 = (float4*)(outb + (size_t)base * O_);
#pragma unroll
                for (int i = 0; i < 8; i++) {
                    int idx = tid + i * 256;           // 2048 float4 = 64 rows x 32
                    o4[idx] = sig4[idx & 31];
                }
            }
            carry = 0;
        } else {
            // exact replay of this chunk (cold path)
            mem = mem0; D = D0;
            int prev = carry;
            for (int tt = 0; tt < 64; tt++) {
                int t = base + tt;
                float rec = 0.f;
                if (prev) {
                    const unsigned* mrow = spkrow + (size_t)(t - 1) * 32;
                    for (int w2 = 0; w2 < 32; w2++) {
                        unsigned msk = mrow[w2];
                        while (msk) {
                            int j = __ffs((int)msk) - 1;
                            rec += wr[w2 * 32 + j];
                            msk &= msk - 1;
                        }
                    }
                }
                float gv = __bfloat162float(gp[(size_t)t * H_]);
                D = fmaf(beta, D, fmaf(s1c, rec, gv));
                mem = fmaf(alpha, mem, D);
                int spike = mem > 1.f;
                if (spike) mem = 0.f;
                unsigned bal = __ballot_sync(0xffffffffu, spike);
                if ((tid & 31) == 0) spkrow[(size_t)t * 32 + sub * 8 + (tid >> 5)] = bal;
                int lor = __syncthreads_or(spike);
                if (tid == 0) {
                    __threadfence();
                    atomicAdd(&step_sync[b * S_ + t], 0x10000u | (unsigned)lor);
                    unsigned v;
                    do { v = *((volatile unsigned*)&step_sync[b * S_ + t]); } while ((v >> 16) < 4u);
                    __threadfence();
                    s_any = (int)(v & 0xFFFFu);
                }
                __syncthreads();
                prev = s_any ? 1 : 0;
                __syncthreads();
                if (sub == 0 && tid < 128) {
                    // out[b,t,tid] = sigmoid(b_out + sum_{j spiking} W_out[tid][j])
                    float acc = b_out[tid];
                    const unsigned* mrow = spkrow + (size_t)t * 32;
                    for (int w2 = 0; w2 < 32; w2++) {
                        unsigned msk = mrow[w2];
                        while (msk) {
                            int j = __ffs((int)msk) - 1;
                            acc += W_out[(size_t)tid * H_ + w2 * 32 + j];
                            msk &= msk - 1;
                        }
                    }
                    outb[(size_t)t * O_ + tid] = sigmoidf_(acc);
                }
            }
            carry = prev;
        }
    }
}

// ---------------------------------------------------------------------------
extern "C" void kernel_launch(void* const* d_in, const int* in_sizes, int n_in,
                              void* d_out, int out_size) {
    const float* x     = (const float*)d_in[0];
    const float* W_in  = (const float*)d_in[1];
    const float* b_in  = (const float*)d_in[2];
    const float* W_rec = (const float*)d_in[3];
    const float* b_rec = (const float*)d_in[4];
    const float* tau_m = (const float*)d_in[5];
    const float* tau_n = (const float*)d_in[6];
    const float* W_out = (const float*)d_in[7];
    const float* b_out = (const float*)d_in[8];
    float* out = (float*)d_out;

    static int attr_done = 0;
    if (!attr_done) {
        cudaFuncSetAttribute(ff_gemm_kernel, cudaFuncAttributeMaxDynamicSharedMemorySize, SMEM_BYTES);
        attr_done = 1;
    }

    cvt_kernel<<<537, 1024>>>(x, W_in, b_in, b_rec, tau_m, tau_n);
    ff_gemm_kernel<<<2048, 256, SMEM_BYTES>>>();
    scan_kernel<<<256, 256>>>(tau_m, tau_n, W_rec, W_out, b_out, out);
}